// round 1
// baseline (speedup 1.0000x reference)
#include <cuda_runtime.h>
#include <math.h>

#define M_FILT 16
#define IMG    96
#define NW     9
#define BATCH  16
#define S      88
#define SP     22
#define FIN    (M_FILT * SP * SP)   // 7744
#define HID    128
#define CLASSES 10

// Scratch (allocation-free rule: __device__ globals)
__device__ float g_pool[BATCH * FIN];     // [b][ip][jp][m]
__device__ float g_hidden[BATCH * HID];

__device__ __forceinline__ float gfun(float xv, float wv, float qv) {
    // log(1.1 + atan(10*(x*w - q))/pi); wv = 10*w, qv = -10*q precomputed
    float u   = fmaf(xv, wv, qv);
    float a   = atanf(u);
    float arg = fmaf(a, 0.3183098861837907f, 1.1f);
    return __logf(arg);
}

// Grid: (11, 11, 16). Block covers positions i in [8*by, 8*by+8), j in [8*bx, 8*bx+8)
// = 2x2 pooled cells, all 16 filters, for batch bz.
__global__ __launch_bounds__(256, 4)
void dendrite_pool_kernel(const float* __restrict__ x,
                          const float* __restrict__ w,
                          const float* __restrict__ q) {
    __shared__ float xs[16 * 16];
    __shared__ float w10[M_FILT * 81];
    __shared__ float q10[M_FILT * 81];
    __shared__ float part[4][4][M_FILT];   // [pool-quadrant][i-row-in-cell][m]

    const int b  = blockIdx.z;
    const int i0 = blockIdx.y * 8;
    const int j0 = blockIdx.x * 8;
    const int t  = threadIdx.x;

    // 16x16 x tile (window reach: 8 + 9 - 1 = 16; i0+15 <= 95, always in bounds)
    {
        int r = t >> 4, c = t & 15;
        xs[t] = x[(b * IMG + i0 + r) * IMG + (j0 + c)];
    }
    for (int k = t; k < M_FILT * 81; k += 256) {
        w10[k] =  10.0f * w[k];
        q10[k] = -10.0f * q[k];
    }
    __syncthreads();

    const int m   = t & 15;
    const int p   = t >> 4;        // 0..15
    const int pq  = p >> 2;        // pool quadrant 0..3  (pr = pq>>1, pc = pq&1)
    const int r4  = p & 3;         // i-row within 4x4 pool cell
    const int li  = 4 * (pq >> 1) + r4;   // local i, 0..7
    const int lj  = 4 * (pq & 1);         // local j base, 0 or 4

    const float* __restrict__ wp = &w10[m * 81];
    const float* __restrict__ qp = &q10[m * 81];

    float a0 = 0.f, a1 = 0.f, a2 = 0.f, a3 = 0.f;

    for (int r = 0; r < 9; ++r) {
        const float* xrow = &xs[(li + r) * 16 + lj];
        #pragma unroll
        for (int c = 0; c < 9; ++c) {
            const float wv = wp[r * 9 + c];
            const float qv = qp[r * 9 + c];
            a0 += gfun(xrow[c + 0], wv, qv);
            a1 += gfun(xrow[c + 1], wv, qv);
            a2 += gfun(xrow[c + 2], wv, qv);
            a3 += gfun(xrow[c + 3], wv, qv);
        }
    }

    // max over the 4 j positions of this thread
    float ymax = fmaxf(fmaxf(a0, a1), fmaxf(a2, a3));
    part[pq][r4][m] = ymax;
    __syncthreads();

    if (t < 64) {
        const int pq2 = t >> 4;
        const int m2  = t & 15;
        float v = fmaxf(fmaxf(part[pq2][0][m2], part[pq2][1][m2]),
                        fmaxf(part[pq2][2][m2], part[pq2][3][m2]));
        const int ip = 2 * blockIdx.y + (pq2 >> 1);
        const int jp = 2 * blockIdx.x + (pq2 & 1);
        g_pool[((b * SP + ip) * SP + jp) * M_FILT + m2] = v;
    }
}

// One warp per (b, o). 7744 = 32 * 242 exactly.
__global__ __launch_bounds__(256)
void fc1_kernel(const float* __restrict__ W, const float* __restrict__ bias) {
    const int warp = (blockIdx.x * blockDim.x + threadIdx.x) >> 5;
    const int lane = threadIdx.x & 31;
    const int b = warp >> 7;        // 128 outputs per batch row
    const int o = warp & 127;
    const float* __restrict__ ip = g_pool + b * FIN;
    const float* __restrict__ wp = W + o * FIN;
    float s = 0.f;
    #pragma unroll 4
    for (int k = lane; k < FIN; k += 32) s = fmaf(ip[k], wp[k], s);
    #pragma unroll
    for (int off = 16; off; off >>= 1) s += __shfl_down_sync(0xFFFFFFFFu, s, off);
    if (lane == 0) g_hidden[b * HID + o] = fmaxf(s + bias[o], 0.f);
}

// Grid: BATCH blocks of 320 threads; warp = class.
__global__ __launch_bounds__(320)
void fc2_kernel(const float* __restrict__ W, const float* __restrict__ bias,
                float* __restrict__ out) {
    const int b    = blockIdx.x;
    const int warp = threadIdx.x >> 5;   // 0..9
    const int lane = threadIdx.x & 31;
    const float* __restrict__ h  = g_hidden + b * HID;
    const float* __restrict__ wp = W + warp * HID;
    float s = 0.f;
    #pragma unroll
    for (int k = lane; k < HID; k += 32) s = fmaf(h[k], wp[k], s);
    #pragma unroll
    for (int off = 16; off; off >>= 1) s += __shfl_down_sync(0xFFFFFFFFu, s, off);
    if (lane == 0) out[b * CLASSES + warp] = s + bias[warp];
}

extern "C" void kernel_launch(void* const* d_in, const int* in_sizes, int n_in,
                              void* d_out, int out_size) {
    const float* x     = (const float*)d_in[0];   // [16,96,96]
    const float* w     = (const float*)d_in[1];   // [16,9,9]
    const float* q     = (const float*)d_in[2];   // [16,9,9]
    const float* fc1_w = (const float*)d_in[3];   // [128,7744]
    const float* fc1_b = (const float*)d_in[4];   // [128]
    const float* fc2_w = (const float*)d_in[5];   // [10,128]
    const float* fc2_b = (const float*)d_in[6];   // [10]
    float* out = (float*)d_out;                   // [16,10]

    dim3 grid1(SP / 2, SP / 2, BATCH);            // (11,11,16)
    dendrite_pool_kernel<<<grid1, 256>>>(x, w, q);

    // 16*128 = 2048 warps, 8 warps/block -> 256 blocks
    fc1_kernel<<<256, 256>>>(fc1_w, fc1_b);

    fc2_kernel<<<BATCH, 320>>>(fc2_w, fc2_b, out);
}

// round 2
// speedup vs baseline: 1.4406x; 1.4406x over previous
#include <cuda_runtime.h>
#include <math.h>

#define M_FILT 16
#define IMG    96
#define BATCH  16
#define S      88
#define SP     22
#define FIN    (M_FILT * SP * SP)   // 7744
#define HID    128
#define CLASSES 10

typedef unsigned long long u64;

__device__ float g_pool[BATCH * FIN];
__device__ float g_hidden[BATCH * HID];

// ---- packed f32x2 helpers (sm_103a) ----
__device__ __forceinline__ u64 PK(float a, float b) {
    u64 r; asm("mov.b64 %0, {%1, %2};" : "=l"(r) : "f"(a), "f"(b)); return r;
}
__device__ __forceinline__ void UPK(u64 v, float& a, float& b) {
    asm("mov.b64 {%0, %1}, %2;" : "=f"(a), "=f"(b) : "l"(v));
}
__device__ __forceinline__ u64 FMA2(u64 a, u64 b, u64 c) {
    u64 d; asm("fma.rn.f32x2 %0, %1, %2, %3;" : "=l"(d) : "l"(a), "l"(b), "l"(c)); return d;
}
__device__ __forceinline__ u64 MUL2(u64 a, u64 b) {
    u64 d; asm("mul.rn.f32x2 %0, %1, %2;" : "=l"(d) : "l"(a), "l"(b)); return d;
}
__device__ __forceinline__ u64 ADD2(u64 a, u64 b) {
    u64 d; asm("add.rn.f32x2 %0, %1, %2;" : "=l"(d) : "l"(a), "l"(b)); return d;
}
__device__ __forceinline__ float RCPA(float x) {
    float r; asm("rcp.approx.ftz.f32 %0, %1;" : "=f"(r) : "f"(x)); return r;
}

// atan(t)/pi minimax coefficients (deg 11 odd), pre-divided by pi
#define PC0  0.3183026472f
#define PC1 -0.1058773494f
#define PC2  0.0616067908f
#define PC3 -0.0370617338f
#define PC4  0.0167600069f
#define PC5 -0.0037309699f

// Grid (11,11,16), block 256. Each thread: 16 filters x (4x4 window rows) layout,
// 4 adjacent j positions processed as two packed f32x2 lanes.
__global__ __launch_bounds__(256, 3)
void dendrite_pool_kernel(const float* __restrict__ x,
                          const float* __restrict__ w,
                          const float* __restrict__ q) {
    __shared__ float2 xs2[16 * 16];          // (x[c], x[c+1]) pairs
    __shared__ float2 w2s[M_FILT * 81];      // (10w, 10w)
    __shared__ float2 q2s[M_FILT * 81];      // (-10q, -10q)
    __shared__ float  part[4][4][M_FILT];

    const int b  = blockIdx.z;
    const int i0 = blockIdx.y * 8;
    const int j0 = blockIdx.x * 8;
    const int t  = threadIdx.x;

    {
        int rr = t >> 4, cc = t & 15;
        const float* xr = &x[(b * IMG + i0 + rr) * IMG + j0];
        float v0 = xr[cc];
        float v1 = (cc < 15) ? xr[cc + 1] : v0;
        xs2[t] = make_float2(v0, v1);
    }
    for (int k = t; k < M_FILT * 81; k += 256) {
        float wv = 10.0f * w[k];
        float qv = -10.0f * q[k];
        w2s[k] = make_float2(wv, wv);
        q2s[k] = make_float2(qv, qv);
    }
    __syncthreads();

    const int m  = t & 15;
    const int p  = t >> 4;
    const int pq = p >> 2;
    const int r4 = p & 3;
    const int li = 4 * (pq >> 1) + r4;
    const int lj = 4 * (pq & 1);

    const u64 K5   = PK(PC5, PC5);
    const u64 K4   = PK(PC4, PC4);
    const u64 K3   = PK(PC3, PC3);
    const u64 K2   = PK(PC2, PC2);
    const u64 K1   = PK(PC1, PC1);
    const u64 K0   = PK(PC0, PC0);
    const u64 QTR  = PK(0.25f, 0.25f);
    const u64 NEG1 = PK(-1.0f, -1.0f);
    const u64 C11  = PK(1.1f, 1.1f);

    u64 accA = PK(1.0f, 1.0f);
    u64 accB = PK(1.0f, 1.0f);

// arg = 1.1 + atan(u)/pi, computed branchless; ACC *= arg (packed, 2 positions)
#define GPAIR(X2, ACC) do {                                                   \
    u64 u_ = FMA2((X2), w2v, q2v);                                            \
    float u0_, u1_; UPK(u_, u0_, u1_);                                        \
    float r0_ = RCPA(u0_), r1_ = RCPA(u1_);                                   \
    float tn0_ = fmaxf(-fabsf(u0_), -fabsf(r0_));   /* -min(|u|,1/|u|) */     \
    float tn1_ = fmaxf(-fabsf(u1_), -fabsf(r1_));                             \
    u64 tn_ = PK(tn0_, tn1_);                                                 \
    u64 t2_ = MUL2(tn_, tn_);                                                 \
    u64 P_  = FMA2(K5, t2_, K4);                                              \
    P_ = FMA2(P_, t2_, K3);                                                   \
    P_ = FMA2(P_, t2_, K2);                                                   \
    P_ = FMA2(P_, t2_, K1);                                                   \
    P_ = FMA2(P_, t2_, K0);                                                   \
    u64 B_ = FMA2(tn_, P_, QTR);          /* 0.25 - t*P'(t^2), >= 0 */        \
    u64 e_ = FMA2(u_, u_, NEG1);          /* u^2 - 1 : sign(|u|-1) */         \
    float e0_, e1_; UPK(e_, e0_, e1_);                                        \
    float b0_, b1_; UPK(B_, b0_, b1_);                                        \
    unsigned s0_ = (__float_as_uint(u0_) ^ __float_as_uint(e0_)) & 0x80000000u;\
    unsigned s1_ = (__float_as_uint(u1_) ^ __float_as_uint(e1_)) & 0x80000000u;\
    float bb0_ = __uint_as_float(__float_as_uint(b0_) ^ s0_);                 \
    float bb1_ = __uint_as_float(__float_as_uint(b1_) ^ s1_);                 \
    float q0_ = __uint_as_float(0x3E800000u | (__float_as_uint(u0_) & 0x80000000u)); \
    float q1_ = __uint_as_float(0x3E800000u | (__float_as_uint(u1_) & 0x80000000u)); \
    u64 arg_ = ADD2(ADD2(PK(bb0_, bb1_), PK(q0_, q1_)), C11);                 \
    ACC = MUL2(ACC, arg_);                                                    \
} while (0)

    for (int r = 0; r < 9; ++r) {
        const float2* __restrict__ xr2 = &xs2[(li + r) * 16 + lj];
        const float2* __restrict__ wr  = &w2s[m * 81 + r * 9];
        const float2* __restrict__ qr  = &q2s[m * 81 + r * 9];
        #pragma unroll
        for (int c = 0; c < 9; ++c) {
            float2 wf = wr[c];
            float2 qf = qr[c];
            u64 w2v = PK(wf.x, wf.y);
            u64 q2v = PK(qf.x, qf.y);
            float2 xa = xr2[c];
            float2 xb = xr2[c + 2];
            u64 XA = PK(xa.x, xa.y);
            u64 XB = PK(xb.x, xb.y);
            GPAIR(XA, accA);
            GPAIR(XB, accB);
        }
    }
#undef GPAIR

    float pa0, pa1, pb0, pb1;
    UPK(accA, pa0, pa1);
    UPK(accB, pb0, pb1);
    // max over 4 j positions in product domain (ln is monotonic)
    part[pq][r4][m] = fmaxf(fmaxf(pa0, pa1), fmaxf(pb0, pb1));
    __syncthreads();

    if (t < 64) {
        const int pq2 = t >> 4;
        const int m2  = t & 15;
        float v = fmaxf(fmaxf(part[pq2][0][m2], part[pq2][1][m2]),
                        fmaxf(part[pq2][2][m2], part[pq2][3][m2]));
        const int ip = 2 * blockIdx.y + (pq2 >> 1);
        const int jp = 2 * blockIdx.x + (pq2 & 1);
        g_pool[((b * SP + ip) * SP + jp) * M_FILT + m2] = __logf(v);
    }
}

__global__ __launch_bounds__(256)
void fc1_kernel(const float* __restrict__ W, const float* __restrict__ bias) {
    const int warp = (blockIdx.x * blockDim.x + threadIdx.x) >> 5;
    const int lane = threadIdx.x & 31;
    const int b = warp >> 7;
    const int o = warp & 127;
    const float* __restrict__ ip = g_pool + b * FIN;
    const float* __restrict__ wp = W + o * FIN;
    float s = 0.f;
    #pragma unroll 4
    for (int k = lane; k < FIN; k += 32) s = fmaf(ip[k], wp[k], s);
    #pragma unroll
    for (int off = 16; off; off >>= 1) s += __shfl_down_sync(0xFFFFFFFFu, s, off);
    if (lane == 0) g_hidden[b * HID + o] = fmaxf(s + bias[o], 0.f);
}

__global__ __launch_bounds__(320)
void fc2_kernel(const float* __restrict__ W, const float* __restrict__ bias,
                float* __restrict__ out) {
    const int b    = blockIdx.x;
    const int warp = threadIdx.x >> 5;
    const int lane = threadIdx.x & 31;
    const float* __restrict__ h  = g_hidden + b * HID;
    const float* __restrict__ wp = W + warp * HID;
    float s = 0.f;
    #pragma unroll
    for (int k = lane; k < HID; k += 32) s = fmaf(h[k], wp[k], s);
    #pragma unroll
    for (int off = 16; off; off >>= 1) s += __shfl_down_sync(0xFFFFFFFFu, s, off);
    if (lane == 0) out[b * CLASSES + warp] = s + bias[warp];
}

extern "C" void kernel_launch(void* const* d_in, const int* in_sizes, int n_in,
                              void* d_out, int out_size) {
    const float* x     = (const float*)d_in[0];
    const float* w     = (const float*)d_in[1];
    const float* q     = (const float*)d_in[2];
    const float* fc1_w = (const float*)d_in[3];
    const float* fc1_b = (const float*)d_in[4];
    const float* fc2_w = (const float*)d_in[5];
    const float* fc2_b = (const float*)d_in[6];
    float* out = (float*)d_out;

    dim3 grid1(SP / 2, SP / 2, BATCH);
    dendrite_pool_kernel<<<grid1, 256>>>(x, w, q);
    fc1_kernel<<<256, 256>>>(fc1_w, fc1_b);
    fc2_kernel<<<BATCH, 320>>>(fc2_w, fc2_b, out);
}